// round 11
// baseline (speedup 1.0000x reference)
#include <cuda_runtime.h>
#include <cuda_fp16.h>
#include <cuda.h>
#include <cstdint>

// ---------------------------------------------------------------------------
// SynthesisLayer on GB300 — mma.sync fp16 implicit GEMM, ldmatrix feeds,
// occupancy-2 mainloop (CTA 128co x 128px, warp 64x32, 2-stage cp.async).
// ---------------------------------------------------------------------------

#define B_    16
#define C_    512
#define HIN   32
#define RESO  64

__device__ float    g_styles[B_ * C_];
__device__ float    g_dcoef [B_ * C_];
__device__ float    g_wsq   [C_ * C_];
__device__ __half   g_pwh   [(size_t)4 * 9 * C_ * C_];  // [ph][tap][co][ci]
// xs, kp-grouped: [b][cg=ci/8][y][x][kp=4 half2 words] (16B per (cg,y,x))
__device__ uint32_t g_xs3   [(size_t)B_ * 64 * HIN * HIN * 4];

__device__ __forceinline__ uint32_t smem_u32(const void* p) {
    uint32_t a;
    asm("{ .reg .u64 t; cvta.to.shared.u64 t, %1; cvt.u32.u64 %0, t; }"
        : "=r"(a) : "l"(p));
    return a;
}
__device__ __forceinline__ void cp16(uint32_t dst, const void* src) {
    asm volatile("cp.async.cg.shared.global [%0], [%1], 16;" :: "r"(dst), "l"(src));
}
__device__ __forceinline__ void cp16z(uint32_t dst, const void* src, bool valid) {
    int sz = valid ? 16 : 0;
    asm volatile("cp.async.cg.shared.global [%0], [%1], 16, %2;"
                 :: "r"(dst), "l"(src), "r"(sz));
}
#define CP_COMMIT() asm volatile("cp.async.commit_group;" ::: "memory")
#define CP_WAIT1()  asm volatile("cp.async.wait_group 1;" ::: "memory")
#define CP_WAIT0()  asm volatile("cp.async.wait_group 0;" ::: "memory")

__device__ __forceinline__ void ldsm4(uint32_t* r, uint32_t addr) {
    asm volatile("ldmatrix.sync.aligned.m8n8.x4.shared.b16 {%0,%1,%2,%3}, [%4];"
                 : "=r"(r[0]), "=r"(r[1]), "=r"(r[2]), "=r"(r[3]) : "r"(addr));
}
__device__ __forceinline__ void ldsm2(uint32_t* r, uint32_t addr) {
    asm volatile("ldmatrix.sync.aligned.m8n8.x2.shared.b16 {%0,%1}, [%2];"
                 : "=r"(r[0]), "=r"(r[1]) : "r"(addr));
}
__device__ __forceinline__ void mma16(float* d, const uint32_t* a, const uint32_t* b) {
    asm volatile(
        "mma.sync.aligned.m16n8k16.row.col.f32.f16.f16.f32 "
        "{%0,%1,%2,%3}, {%4,%5,%6,%7}, {%8,%9}, {%0,%1,%2,%3};"
        : "+f"(d[0]), "+f"(d[1]), "+f"(d[2]), "+f"(d[3])
        : "r"(a[0]), "r"(a[1]), "r"(a[2]), "r"(a[3]),
          "r"(b[0]), "r"(b[1]));
}

// ======================= setup kernels =====================================
__global__ void k_styles(const float* __restrict__ w,
                         const float* __restrict__ aw,
                         const float* __restrict__ ab) {
    int gw = blockIdx.x * 8 + (threadIdx.x >> 5);
    int lane = threadIdx.x & 31;
    int b = gw >> 9, j = gw & 511;
    const float4* ar = (const float4*)(aw + (size_t)j * C_);
    const float4* wr = (const float4*)(w + (size_t)b * C_);
    float s = 0.f;
    #pragma unroll
    for (int i = 0; i < 4; i++) {
        float4 a = ar[lane + 32 * i], x = wr[lane + 32 * i];
        s += a.x * x.x + a.y * x.y + a.z * x.z + a.w * x.w;
    }
    #pragma unroll
    for (int o = 16; o; o >>= 1) s += __shfl_xor_sync(~0u, s, o);
    if (lane == 0) g_styles[gw] = s * 0.04419417382415922f + ab[j];
}

// phase-composed 3x3 kernels (half2-coalesced writes) + wsq table
__global__ void k_pw(const float* __restrict__ weight) {
    int co = blockIdx.x, t = threadIdx.x;    // t = ci pair 0..255
    int ci0 = 2 * t;
    float wgt[2][3][3];
    float wsq[2] = {0.f, 0.f};
    #pragma unroll
    for (int h = 0; h < 2; h++) {
        const float* p = weight + ((size_t)co * C_ + ci0 + h) * 9;
        #pragma unroll
        for (int k = 0; k < 9; k++) {
            float v = p[k];
            wgt[h][k / 3][k % 3] = v;
            wsq[h] += v * v;
        }
    }
    *(float2*)(g_wsq + (size_t)co * C_ + ci0) = make_float2(wsq[0], wsq[1]);
    const float cc[4] = {1.f, 3.f, 3.f, 1.f};
    #pragma unroll
    for (int ry = 0; ry < 2; ry++)
    #pragma unroll
    for (int rx = 0; rx < 2; rx++) {
        int ph = ry * 2 + rx;
        #pragma unroll
        for (int dyi = 0; dyi < 3; dyi++)
        #pragma unroll
        for (int dxi = 0; dxi < 3; dxi++) {
            float v[2] = {0.f, 0.f};
            #pragma unroll
            for (int sy = 0; sy < 3; sy++) {
                int uy = 2 * dyi + 1 - ry - sy;
                if (uy < 0 || uy > 3) continue;
                #pragma unroll
                for (int sx = 0; sx < 3; sx++) {
                    int ux = 2 * dxi + 1 - rx - sx;
                    if (ux < 0 || ux > 3) continue;
                    float c = cc[uy] * cc[ux];
                    v[0] += wgt[0][2 - sy][2 - sx] * c;
                    v[1] += wgt[1][2 - sy][2 - sx] * c;
                }
            }
            int tap = dyi * 3 + dxi;
            __half2 h = __floats2half2_rn(v[0] * 0.0625f, v[1] * 0.0625f);
            *(__half2*)(g_pwh + (((size_t)(ph * 9 + tap) * C_) + co) * C_ + ci0) = h;
        }
    }
}

__global__ void k_dcoef() {
    int gw = blockIdx.x * 8 + (threadIdx.x >> 5);  // (b, co)
    int lane = threadIdx.x & 31;
    int b = gw >> 9, co = gw & 511;
    const float4* wq = (const float4*)(g_wsq + (size_t)co * C_);
    const float4* sp = (const float4*)(g_styles + b * C_);
    float s = 0.f;
    #pragma unroll
    for (int i = 0; i < 4; i++) {
        float4 a = wq[lane + 32 * i], x = sp[lane + 32 * i];
        s += a.x * x.x * x.x + a.y * x.y * x.y + a.z * x.z * x.z + a.w * x.w * x.w;
    }
    #pragma unroll
    for (int o = 16; o; o >>= 1) s += __shfl_xor_sync(~0u, s, o);
    if (lane == 0) g_dcoef[gw] = rsqrtf(s + 1e-8f);
}

// modulated input -> kp-grouped half2 layout
__global__ void k_xs(const float* __restrict__ x) {
    int bg = blockIdx.x;                      // b*64 + cg
    int b = bg >> 6, cg = bg & 63;
    float st[8];
    #pragma unroll
    for (int j = 0; j < 8; j++) st[j] = g_styles[b * C_ + cg * 8 + j];
    const float* src = x + ((size_t)(b * C_ + cg * 8)) * (HIN * HIN);
    uint4* dst = (uint4*)g_xs3 + (size_t)bg * (HIN * HIN);
    for (int i = threadIdx.x; i < HIN * HIN; i += 256) {
        uint4 o;
        __half2 h0 = __floats2half2_rn(src[i] * st[0], src[i + 1024] * st[1]);
        __half2 h1 = __floats2half2_rn(src[i + 2048] * st[2], src[i + 3072] * st[3]);
        __half2 h2 = __floats2half2_rn(src[i + 4096] * st[4], src[i + 5120] * st[5]);
        __half2 h3 = __floats2half2_rn(src[i + 6144] * st[6], src[i + 7168] * st[7]);
        o.x = *(uint32_t*)&h0; o.y = *(uint32_t*)&h1;
        o.z = *(uint32_t*)&h2; o.w = *(uint32_t*)&h3;
        dst[i] = o;
    }
}

// ======================= main MMA conv =====================================
// CTA 128co x 128px (4 q-rows), 256 threads (8 warps, 2M x 4N), warp 64x32.
// K loop: 32 chunks of 16 ci (2 cg); A smem kseg-major (no padding);
// 2-stage cp.async; occupancy 2.
#define NCH   32
#define A_WORDS (9 * 2 * 128 * 4)     // 9216 u32: [tap][kseg][co][16B]
#define A_TAP_BYTES (2 * 128 * 16)    // 4096
#define B_WORDS (2 * 6 * 34 * 4)      // 1632 u32: [cg][row(6)][col(34)][16B]
#define BUF_WORDS (A_WORDS + B_WORDS) // 10848
#define BUF_BYTES (BUF_WORDS * 4)     // 43392
#define NSTAGE 2
#define SMEM_DYN (NSTAGE * BUF_BYTES) // 86784 per CTA (x2 CTAs = 173568)

__global__ void __launch_bounds__(256, 2)
k_conv_mma(const float* __restrict__ bias,
           const float* __restrict__ noise,
           const float* __restrict__ nstr,
           float* __restrict__ out) {
    extern __shared__ uint32_t dsm[];
    const uint32_t sbase = smem_u32(dsm);

    const int tid  = threadIdx.x;
    const int lane = tid & 31;
    const int wid  = tid >> 5;
    const int wm   = (wid & 1) * 64;          // warp co offset
    const int wn   = (wid >> 1) * 32;         // warp pix offset
    const int g    = lane >> 2;
    const int tg   = lane & 3;

    const int co0 = blockIdx.x * 128;
    const int qy0 = blockIdx.y * 4;           // 4 q-rows per CTA
    const int bz  = blockIdx.z;
    const int b   = bz >> 2, ph = bz & 3;
    const int ry  = ph >> 1, rx = ph & 1;

    const uint32_t* xs_b = g_xs3 + (size_t)(b * 64) * (HIN * HIN * 4);
    const __half*   pw_p = g_pwh + (size_t)ph * 9 * C_ * C_;

    // ldmatrix lane address bases
    const int q  = lane >> 3;                 // matrix index for x4
    const uint32_t a_lane = (uint32_t)((q >> 1) * 2048 +
                                       (wm + (q & 1) * 8 + (lane & 7)) * 16);
    const uint32_t b_lane = (uint32_t)(((lane >> 3) & 1) * (6 * 34 * 16) +
                                       ((wn >> 5) * 34 + (lane & 7)) * 16);

    float acc[4][4][4];
    #pragma unroll
    for (int mf = 0; mf < 4; mf++)
        #pragma unroll
        for (int nf = 0; nf < 4; nf++)
            #pragma unroll
            for (int r = 0; r < 4; r++) acc[mf][nf][r] = 0.f;

    // ---- chunk loader (cp.async into stage s); chunk = 16 ci = 2 kseg ----
    auto load_chunk = [&](int it, int s) {
        const int ci0 = it * 16;
        const uint32_t ab = sbase + s * BUF_BYTES;
        const uint32_t bb = ab + A_WORDS * 4;
        // A: [tap][kseg][co] 16B rows, linear dst, 2304 cp16
        #pragma unroll
        for (int j = 0; j < 9; j++) {
            int idx  = j * 256 + tid;         // 0..2303
            int tap  = idx >> 8;
            int rem  = idx & 255;
            int kseg = rem >> 7;
            int co   = rem & 127;
            cp16(ab + (uint32_t)(idx * 16),
                 pw_p + ((size_t)tap * C_ + co0 + co) * C_ + ci0 + kseg * 8);
        }
        // B: 2 cg x 6 rows x 34 cols, one cp16 each (408), linear dst
        #pragma unroll
        for (int j = 0; j < 2; j++) {
            int e = j * 256 + tid;
            if (j == 1 && e >= 408) break;
            int cg  = e / 204;
            int rem = e - cg * 204;
            int row = rem / 34;
            int col = rem - row * 34;
            int gy = qy0 + row - 1;
            int gx = col - 1;
            bool ok = ((unsigned)gy < (unsigned)HIN) & ((unsigned)gx < (unsigned)HIN);
            cp16z(bb + (uint32_t)(e * 16),
                  xs_b + (((size_t)(it * 2 + cg)) * (HIN * HIN) + gy * HIN + gx) * 4, ok);
        }
    };

    load_chunk(0, 0); CP_COMMIT();

    int stage = 0;
    for (int it = 0; it < NCH; ++it) {
        __syncthreads();
        if (it + 1 < NCH) {
            load_chunk(it + 1, stage ^ 1);
            CP_COMMIT();
            CP_WAIT1();
        } else {
            CP_WAIT0();
        }
        __syncthreads();

        const uint32_t sA = sbase + stage * BUF_BYTES;
        const uint32_t sBb = sA + A_WORDS * 4;

        #pragma unroll
        for (int tap = 0; tap < 9; tap++) {
            const int dy = tap / 3, dx = tap - 3 * (tap / 3);
            const uint32_t at = sA + tap * A_TAP_BYTES + a_lane;
            uint32_t af[4][4];
            #pragma unroll
            for (int mf = 0; mf < 4; mf++)
                ldsm4(af[mf], at + mf * 256);            // 16 rows x 16B
            const uint32_t bt = sBb + b_lane + (uint32_t)((dy * 34 + dx) * 16);
            #pragma unroll
            for (int nf = 0; nf < 4; nf++) {
                uint32_t bf[2];
                ldsm2(bf, bt + (uint32_t)(nf * 8 * 16));
                #pragma unroll
                for (int mf = 0; mf < 4; mf++)
                    mma16(acc[mf][nf], af[mf], bf);
            }
        }

        stage ^= 1;
    }

    // ---- epilogue: demod + noise + bias + lrelu*sqrt(2) ----
    const float ns = *nstr;
    #pragma unroll
    for (int mf = 0; mf < 4; mf++) {
        int co_a = co0 + wm + mf * 16 + g;
        int co_b = co_a + 8;
        float dca = g_dcoef[b * C_ + co_a], bva = bias[co_a];
        float dcb = g_dcoef[b * C_ + co_b], bvb = bias[co_b];
        float* oa = out + ((size_t)(b * C_ + co_a) * RESO) * RESO;
        float* ob = out + ((size_t)(b * C_ + co_b) * RESO) * RESO;
        #pragma unroll
        for (int nf = 0; nf < 4; nf++) {
            int n0 = wn + nf * 8 + 2 * tg;
            int oy = 2 * (qy0 + (n0 >> 5)) + ry;
            int ox = 2 * (n0 & 31) + rx;
            int base = oy * RESO + ox;
            float nz0 = noise[base] * ns;
            float nz1 = noise[base + 2] * ns;
            float v0 = acc[mf][nf][0] * dca + nz0 + bva;
            float v1 = acc[mf][nf][1] * dca + nz1 + bva;
            float v2 = acc[mf][nf][2] * dcb + nz0 + bvb;
            float v3 = acc[mf][nf][3] * dcb + nz1 + bvb;
            v0 = (v0 >= 0.f ? v0 : 0.2f * v0) * 1.4142135623730951f;
            v1 = (v1 >= 0.f ? v1 : 0.2f * v1) * 1.4142135623730951f;
            v2 = (v2 >= 0.f ? v2 : 0.2f * v2) * 1.4142135623730951f;
            v3 = (v3 >= 0.f ? v3 : 0.2f * v3) * 1.4142135623730951f;
            oa[base]     = v0;
            oa[base + 2] = v1;
            ob[base]     = v2;
            ob[base + 2] = v3;
        }
    }
}

// ======================= launch ============================================
extern "C" void kernel_launch(void* const* d_in, const int* in_sizes, int n_in,
                              void* d_out, int out_size) {
    const float* x      = (const float*)d_in[0];
    const float* w      = (const float*)d_in[1];
    const float* aw     = (const float*)d_in[2];
    const float* ab     = (const float*)d_in[3];
    const float* weight = (const float*)d_in[4];
    const float* bias   = (const float*)d_in[5];
    const float* noise  = (const float*)d_in[6];
    const float* nstr   = (const float*)d_in[7];
    float* out = (float*)d_out;

    static bool attr_set = false;
    if (!attr_set) {
        cudaFuncSetAttribute(k_conv_mma,
                             cudaFuncAttributeMaxDynamicSharedMemorySize, SMEM_DYN);
        attr_set = true;
    }

    k_styles<<<(B_ * C_) / 8, 256>>>(w, aw, ab);
    k_pw<<<C_, 256>>>(weight);
    k_dcoef<<<(B_ * C_) / 8, 256>>>();
    k_xs<<<B_ * 64, 256>>>(x);
    k_conv_mma<<<dim3(4, 8, B_ * 4), 256, SMEM_DYN>>>(bias, noise, nstr, out);
}

// round 12
// speedup vs baseline: 1.4077x; 1.4077x over previous
#include <cuda_runtime.h>
#include <cuda_fp16.h>
#include <cuda.h>
#include <cstdint>

// ---------------------------------------------------------------------------
// SynthesisLayer on GB300 — mma.sync fp16 implicit GEMM, ldmatrix operand
// feeds (A row-major 16x16 x4; B via kp-grouped xs layout, non-trans x4).
// R12 = R10 (best known) + epilogue noise hoist. R11 occ-2 variant reverted.
// ---------------------------------------------------------------------------

#define B_    16
#define C_    512
#define HIN   32
#define RESO  64

__device__ float    g_styles[B_ * C_];
__device__ float    g_dcoef [B_ * C_];
__device__ float    g_wsq   [C_ * C_];
__device__ __half   g_pwh   [(size_t)4 * 9 * C_ * C_];  // [ph][tap][co][ci]
// xs, kp-grouped: [b][cg=ci/8][y][x][kp=4 half2 words] (16B per (cg,y,x))
__device__ uint32_t g_xs3   [(size_t)B_ * 64 * HIN * HIN * 4];

__device__ __forceinline__ uint32_t smem_u32(const void* p) {
    uint32_t a;
    asm("{ .reg .u64 t; cvta.to.shared.u64 t, %1; cvt.u32.u64 %0, t; }"
        : "=r"(a) : "l"(p));
    return a;
}
__device__ __forceinline__ void cp16(uint32_t dst, const void* src) {
    asm volatile("cp.async.cg.shared.global [%0], [%1], 16;" :: "r"(dst), "l"(src));
}
__device__ __forceinline__ void cp16z(uint32_t dst, const void* src, bool valid) {
    int sz = valid ? 16 : 0;
    asm volatile("cp.async.cg.shared.global [%0], [%1], 16, %2;"
                 :: "r"(dst), "l"(src), "r"(sz));
}
#define CP_COMMIT() asm volatile("cp.async.commit_group;" ::: "memory")
#define CP_WAIT1()  asm volatile("cp.async.wait_group 1;" ::: "memory")
#define CP_WAIT0()  asm volatile("cp.async.wait_group 0;" ::: "memory")

__device__ __forceinline__ void ldsm4(uint32_t* r, uint32_t addr) {
    asm volatile("ldmatrix.sync.aligned.m8n8.x4.shared.b16 {%0,%1,%2,%3}, [%4];"
                 : "=r"(r[0]), "=r"(r[1]), "=r"(r[2]), "=r"(r[3]) : "r"(addr));
}
__device__ __forceinline__ void mma16(float* d, const uint32_t* a, const uint32_t* b) {
    asm volatile(
        "mma.sync.aligned.m16n8k16.row.col.f32.f16.f16.f32 "
        "{%0,%1,%2,%3}, {%4,%5,%6,%7}, {%8,%9}, {%0,%1,%2,%3};"
        : "+f"(d[0]), "+f"(d[1]), "+f"(d[2]), "+f"(d[3])
        : "r"(a[0]), "r"(a[1]), "r"(a[2]), "r"(a[3]),
          "r"(b[0]), "r"(b[1]));
}

// ======================= setup kernels =====================================
__global__ void k_styles(const float* __restrict__ w,
                         const float* __restrict__ aw,
                         const float* __restrict__ ab) {
    int gw = blockIdx.x * 8 + (threadIdx.x >> 5);
    int lane = threadIdx.x & 31;
    int b = gw >> 9, j = gw & 511;
    const float4* ar = (const float4*)(aw + (size_t)j * C_);
    const float4* wr = (const float4*)(w + (size_t)b * C_);
    float s = 0.f;
    #pragma unroll
    for (int i = 0; i < 4; i++) {
        float4 a = ar[lane + 32 * i], x = wr[lane + 32 * i];
        s += a.x * x.x + a.y * x.y + a.z * x.z + a.w * x.w;
    }
    #pragma unroll
    for (int o = 16; o; o >>= 1) s += __shfl_xor_sync(~0u, s, o);
    if (lane == 0) g_styles[gw] = s * 0.04419417382415922f + ab[j];
}

// phase-composed 3x3 kernels (half2-coalesced writes) + wsq table
__global__ void k_pw(const float* __restrict__ weight) {
    int co = blockIdx.x, t = threadIdx.x;    // t = ci pair 0..255
    int ci0 = 2 * t;
    float wgt[2][3][3];
    float wsq[2] = {0.f, 0.f};
    #pragma unroll
    for (int h = 0; h < 2; h++) {
        const float* p = weight + ((size_t)co * C_ + ci0 + h) * 9;
        #pragma unroll
        for (int k = 0; k < 9; k++) {
            float v = p[k];
            wgt[h][k / 3][k % 3] = v;
            wsq[h] += v * v;
        }
    }
    *(float2*)(g_wsq + (size_t)co * C_ + ci0) = make_float2(wsq[0], wsq[1]);
    const float cc[4] = {1.f, 3.f, 3.f, 1.f};
    #pragma unroll
    for (int ry = 0; ry < 2; ry++)
    #pragma unroll
    for (int rx = 0; rx < 2; rx++) {
        int ph = ry * 2 + rx;
        #pragma unroll
        for (int dyi = 0; dyi < 3; dyi++)
        #pragma unroll
        for (int dxi = 0; dxi < 3; dxi++) {
            float v[2] = {0.f, 0.f};
            #pragma unroll
            for (int sy = 0; sy < 3; sy++) {
                int uy = 2 * dyi + 1 - ry - sy;
                if (uy < 0 || uy > 3) continue;
                #pragma unroll
                for (int sx = 0; sx < 3; sx++) {
                    int ux = 2 * dxi + 1 - rx - sx;
                    if (ux < 0 || ux > 3) continue;
                    float c = cc[uy] * cc[ux];
                    v[0] += wgt[0][2 - sy][2 - sx] * c;
                    v[1] += wgt[1][2 - sy][2 - sx] * c;
                }
            }
            int tap = dyi * 3 + dxi;
            __half2 h = __floats2half2_rn(v[0] * 0.0625f, v[1] * 0.0625f);
            *(__half2*)(g_pwh + (((size_t)(ph * 9 + tap) * C_) + co) * C_ + ci0) = h;
        }
    }
}

__global__ void k_dcoef() {
    int gw = blockIdx.x * 8 + (threadIdx.x >> 5);  // (b, co)
    int lane = threadIdx.x & 31;
    int b = gw >> 9, co = gw & 511;
    const float4* wq = (const float4*)(g_wsq + (size_t)co * C_);
    const float4* sp = (const float4*)(g_styles + b * C_);
    float s = 0.f;
    #pragma unroll
    for (int i = 0; i < 4; i++) {
        float4 a = wq[lane + 32 * i], x = sp[lane + 32 * i];
        s += a.x * x.x * x.x + a.y * x.y * x.y + a.z * x.z * x.z + a.w * x.w * x.w;
    }
    #pragma unroll
    for (int o = 16; o; o >>= 1) s += __shfl_xor_sync(~0u, s, o);
    if (lane == 0) g_dcoef[gw] = rsqrtf(s + 1e-8f);
}

// modulated input -> kp-grouped half2 layout
__global__ void k_xs(const float* __restrict__ x) {
    int bg = blockIdx.x;                      // b*64 + cg
    int b = bg >> 6, cg = bg & 63;
    float st[8];
    #pragma unroll
    for (int j = 0; j < 8; j++) st[j] = g_styles[b * C_ + cg * 8 + j];
    const float* src = x + ((size_t)(b * C_ + cg * 8)) * (HIN * HIN);
    uint4* dst = (uint4*)g_xs3 + (size_t)bg * (HIN * HIN);
    for (int i = threadIdx.x; i < HIN * HIN; i += 256) {
        uint4 o;
        __half2 h0 = __floats2half2_rn(src[i] * st[0], src[i + 1024] * st[1]);
        __half2 h1 = __floats2half2_rn(src[i + 2048] * st[2], src[i + 3072] * st[3]);
        __half2 h2 = __floats2half2_rn(src[i + 4096] * st[4], src[i + 5120] * st[5]);
        __half2 h3 = __floats2half2_rn(src[i + 6144] * st[6], src[i + 7168] * st[7]);
        o.x = *(uint32_t*)&h0; o.y = *(uint32_t*)&h1;
        o.z = *(uint32_t*)&h2; o.w = *(uint32_t*)&h3;
        dst[i] = o;
    }
}

// ======================= main MMA conv =====================================
// CTA 128co x 256px (8 q-rows), 256 threads (8 warps, 2M x 4N), warp 64x64.
// K loop: 16 chunks of 32 ci (4 cg groups); ldmatrix operand loads.
#define NCH   16
#define ACO2  20                      // A co stride (words): 16 data + 4 pad
#define A_WORDS (9 * 128 * ACO2)      // 23040 u32
#define A_TAP_BYTES (128 * ACO2 * 4)  // 10240
#define B_WORDS (4 * 340 * 4)         // 5440 u32 (cg x 10 x 34 x kp)
#define BUF_WORDS (A_WORDS + B_WORDS) // 28480
#define BUF_BYTES (BUF_WORDS * 4)     // 113920
#define NSTAGE 2
#define SMEM_DYN (NSTAGE * BUF_BYTES) // 227840

__global__ void __launch_bounds__(256, 1)
k_conv_mma(const float* __restrict__ bias,
           const float* __restrict__ noise,
           const float* __restrict__ nstr,
           float* __restrict__ out) {
    extern __shared__ uint32_t dsm[];
    const uint32_t sbase = smem_u32(dsm);

    const int tid  = threadIdx.x;
    const int lane = tid & 31;
    const int wid  = tid >> 5;
    const int wm   = (wid & 1) * 64;          // warp co offset
    const int wn   = (wid >> 1) * 64;         // warp pix offset
    const int g    = lane >> 2;
    const int tg   = lane & 3;

    const int co0 = blockIdx.x * 128;
    const int qy0 = blockIdx.y * 8;
    const int bz  = blockIdx.z;
    const int b   = bz >> 2, ph = bz & 3;
    const int ry  = ph >> 1, rx = ph & 1;

    const uint32_t* xs_b = g_xs3 + (size_t)(b * 64) * (HIN * HIN * 4);
    const __half*   pw_p = g_pwh + (size_t)ph * 9 * C_ * C_;

    // ldmatrix lane address bases (byte offsets within tile regions)
    const uint32_t a_lane = (uint32_t)((wm + (lane & 15)) * (ACO2 * 4) + (lane >> 4) * 16);
    const uint32_t b_lane = (uint32_t)((lane >> 3) * (340 * 16) + (lane & 7) * 16);

    float acc[4][8][4];
    #pragma unroll
    for (int mf = 0; mf < 4; mf++)
        #pragma unroll
        for (int nf = 0; nf < 8; nf++)
            #pragma unroll
            for (int r = 0; r < 4; r++) acc[mf][nf][r] = 0.f;

    // ---- chunk loader (cp.async into stage s); chunk = 32 ci = 4 cg ----
    auto load_chunk = [&](int it, int s) {
        const int ci0 = it * 32;
        const uint32_t ab = sbase + s * BUF_BYTES;
        const uint32_t bb = ab + A_WORDS * 4;
        // A: 9 taps x 128 co x 32 ci (4 cp16 per co-row; row stride 20 words)
        #pragma unroll
        for (int j = 0; j < 18; j++) {
            int idx = j * 256 + tid;          // 0..4607
            int row = idx >> 2;               // tap*128 + co
            int h   = idx & 3;
            int tap = row >> 7;
            int co  = row & 127;
            cp16(ab + (uint32_t)((row * ACO2 + h * 4) * 4),
                 pw_p + ((size_t)tap * C_ + co0 + co) * C_ + ci0 + h * 8);
        }
        // B: 4 cg x 10 rows x 34 cols, one cp16 per (cg,y,x) position
        #pragma unroll
        for (int j = 0; j < 6; j++) {
            int e = j * 256 + tid;
            if (j == 5 && e >= 1360) break;
            int cg  = e / 340;
            int rem = e - cg * 340;
            int row = rem / 34;
            int col = rem - row * 34;
            int gy = qy0 + row - 1;
            int gx = col - 1;
            bool ok = ((unsigned)gy < (unsigned)HIN) & ((unsigned)gx < (unsigned)HIN);
            cp16z(bb + (uint32_t)((cg * 340 + row * 34 + col) * 16),
                  xs_b + (((size_t)(it * 4 + cg)) * (HIN * HIN) + gy * HIN + gx) * 4, ok);
        }
    };

    load_chunk(0, 0); CP_COMMIT();

    int stage = 0;
    for (int it = 0; it < NCH; ++it) {
        __syncthreads();
        if (it + 1 < NCH) {
            load_chunk(it + 1, stage ^ 1);
            CP_COMMIT();
            CP_WAIT1();
        } else {
            CP_WAIT0();
        }
        __syncthreads();

        const uint32_t sA = sbase + stage * BUF_BYTES;
        const uint32_t sBb = sA + A_WORDS * 4;

        #pragma unroll
        for (int tap = 0; tap < 9; tap++) {
            const int dy = tap / 3, dx = tap - 3 * (tap / 3);
            const uint32_t at = sA + tap * A_TAP_BYTES + a_lane;
            uint32_t af[4][8];
            #pragma unroll
            for (int mf = 0; mf < 4; mf++) {
                ldsm4(af[mf],     at + mf * (16 * ACO2 * 4));        // kseg0
                ldsm4(af[mf] + 4, at + mf * (16 * ACO2 * 4) + 32);   // kseg1
            }
            const uint32_t bt = sBb + b_lane + (uint32_t)((dy * 34 + dx) * 16);
            #pragma unroll
            for (int nf = 0; nf < 8; nf++) {
                int n0 = wn + nf * 8;
                uint32_t bf[4];
                ldsm4(bf, bt + (uint32_t)((((n0 >> 5) * 34) + (n0 & 31)) * 16));
                #pragma unroll
                for (int mf = 0; mf < 4; mf++) {
                    mma16(acc[mf][nf], af[mf], bf);
                    mma16(acc[mf][nf], af[mf] + 4, bf + 2);
                }
            }
        }

        stage ^= 1;
    }

    // ---- epilogue: demod + noise + bias + lrelu*sqrt(2) ----
    const float ns = *nstr;
    int baseo[8];
    float nz0[8], nz1[8];
    #pragma unroll
    for (int nf = 0; nf < 8; nf++) {
        int n0 = wn + nf * 8 + 2 * tg;
        int oy = 2 * (qy0 + (n0 >> 5)) + ry;
        int ox = 2 * (n0 & 31) + rx;
        baseo[nf] = oy * RESO + ox;
        nz0[nf] = noise[baseo[nf]] * ns;
        nz1[nf] = noise[baseo[nf] + 2] * ns;
    }
    #pragma unroll
    for (int mf = 0; mf < 4; mf++) {
        int co_a = co0 + wm + mf * 16 + g;
        int co_b = co_a + 8;
        float dca = g_dcoef[b * C_ + co_a], bva = bias[co_a];
        float dcb = g_dcoef[b * C_ + co_b], bvb = bias[co_b];
        float* oa = out + ((size_t)(b * C_ + co_a) * RESO) * RESO;
        float* ob = out + ((size_t)(b * C_ + co_b) * RESO) * RESO;
        #pragma unroll
        for (int nf = 0; nf < 8; nf++) {
            int base = baseo[nf];
            float v0 = acc[mf][nf][0] * dca + nz0[nf] + bva;
            float v1 = acc[mf][nf][1] * dca + nz1[nf] + bva;
            float v2 = acc[mf][nf][2] * dcb + nz0[nf] + bvb;
            float v3 = acc[mf][nf][3] * dcb + nz1[nf] + bvb;
            v0 = (v0 >= 0.f ? v0 : 0.2f * v0) * 1.4142135623730951f;
            v1 = (v1 >= 0.f ? v1 : 0.2f * v1) * 1.4142135623730951f;
            v2 = (v2 >= 0.f ? v2 : 0.2f * v2) * 1.4142135623730951f;
            v3 = (v3 >= 0.f ? v3 : 0.2f * v3) * 1.4142135623730951f;
            oa[base]     = v0;
            oa[base + 2] = v1;
            ob[base]     = v2;
            ob[base + 2] = v3;
        }
    }
}

// ======================= launch ============================================
extern "C" void kernel_launch(void* const* d_in, const int* in_sizes, int n_in,
                              void* d_out, int out_size) {
    const float* x      = (const float*)d_in[0];
    const float* w      = (const float*)d_in[1];
    const float* aw     = (const float*)d_in[2];
    const float* ab     = (const float*)d_in[3];
    const float* weight = (const float*)d_in[4];
    const float* bias   = (const float*)d_in[5];
    const float* noise  = (const float*)d_in[6];
    const float* nstr   = (const float*)d_in[7];
    float* out = (float*)d_out;

    static bool attr_set = false;
    if (!attr_set) {
        cudaFuncSetAttribute(k_conv_mma,
                             cudaFuncAttributeMaxDynamicSharedMemorySize, SMEM_DYN);
        attr_set = true;
    }

    k_styles<<<(B_ * C_) / 8, 256>>>(w, aw, ab);
    k_pw<<<C_, 256>>>(weight);
    k_dcoef<<<(B_ * C_) / 8, 256>>>();
    k_xs<<<B_ * 64, 256>>>(x);
    k_conv_mma<<<dim3(4, 4, B_ * 4), 256, SMEM_DYN>>>(bias, noise, nstr, out);
}

// round 16
// speedup vs baseline: 1.4171x; 1.0067x over previous
#include <cuda_runtime.h>
#include <cuda_fp16.h>
#include <cuda.h>
#include <cstdint>

// ---------------------------------------------------------------------------
// SynthesisLayer on GB300 — mma.sync fp16 implicit GEMM, ldmatrix operand
// feeds. R14 = R12 mainloop (best known, 794us) + setup fused 4->2 kernels
// with CORRECT sub-grid sizes (R13 carved 128 blocks where 1024 were needed).
// ---------------------------------------------------------------------------

#define B_    16
#define C_    512
#define HIN   32
#define RESO  64

__device__ float    g_styles[B_ * C_];
__device__ float    g_dcoef [B_ * C_];
__device__ float    g_wsq   [C_ * C_];
__device__ __half   g_pwh   [(size_t)4 * 9 * C_ * C_];  // [ph][tap][co][ci]
// xs, kp-grouped: [b][cg=ci/8][y][x][kp=4 half2 words] (16B per (cg,y,x))
__device__ uint32_t g_xs3   [(size_t)B_ * 64 * HIN * HIN * 4];

__device__ __forceinline__ uint32_t smem_u32(const void* p) {
    uint32_t a;
    asm("{ .reg .u64 t; cvta.to.shared.u64 t, %1; cvt.u32.u64 %0, t; }"
        : "=r"(a) : "l"(p));
    return a;
}
__device__ __forceinline__ void cp16(uint32_t dst, const void* src) {
    asm volatile("cp.async.cg.shared.global [%0], [%1], 16;" :: "r"(dst), "l"(src));
}
__device__ __forceinline__ void cp16z(uint32_t dst, const void* src, bool valid) {
    int sz = valid ? 16 : 0;
    asm volatile("cp.async.cg.shared.global [%0], [%1], 16, %2;"
                 :: "r"(dst), "l"(src), "r"(sz));
}
#define CP_COMMIT() asm volatile("cp.async.commit_group;" ::: "memory")
#define CP_WAIT1()  asm volatile("cp.async.wait_group 1;" ::: "memory")
#define CP_WAIT0()  asm volatile("cp.async.wait_group 0;" ::: "memory")

__device__ __forceinline__ void ldsm4(uint32_t* r, uint32_t addr) {
    asm volatile("ldmatrix.sync.aligned.m8n8.x4.shared.b16 {%0,%1,%2,%3}, [%4];"
                 : "=r"(r[0]), "=r"(r[1]), "=r"(r[2]), "=r"(r[3]) : "r"(addr));
}
__device__ __forceinline__ void mma16(float* d, const uint32_t* a, const uint32_t* b) {
    asm volatile(
        "mma.sync.aligned.m16n8k16.row.col.f32.f16.f16.f32 "
        "{%0,%1,%2,%3}, {%4,%5,%6,%7}, {%8,%9}, {%0,%1,%2,%3};"
        : "+f"(d[0]), "+f"(d[1]), "+f"(d[2]), "+f"(d[3])
        : "r"(a[0]), "r"(a[1]), "r"(a[2]), "r"(a[3]),
          "r"(b[0]), "r"(b[1]));
}

// ======================= fused setup kernels ===============================
// prep1: blocks [0,1024): styles ; blocks [1024,1536): phase weights + wsq.
#define P1_STYLES 1024
__global__ void k_prep1(const float* __restrict__ w,
                        const float* __restrict__ aw,
                        const float* __restrict__ ab,
                        const float* __restrict__ weight) {
    if (blockIdx.x < P1_STYLES) {
        // ---- styles[b][j] = dot(w[b], A[j]) / sqrt(512) + bias[j] ----
        int gw = blockIdx.x * 8 + (threadIdx.x >> 5);   // 8192 warps total
        int lane = threadIdx.x & 31;
        int b = gw >> 9, j = gw & 511;
        const float4* ar = (const float4*)(aw + (size_t)j * C_);
        const float4* wr = (const float4*)(w + (size_t)b * C_);
        float s = 0.f;
        #pragma unroll
        for (int i = 0; i < 4; i++) {
            float4 a = ar[lane + 32 * i], x = wr[lane + 32 * i];
            s += a.x * x.x + a.y * x.y + a.z * x.z + a.w * x.w;
        }
        #pragma unroll
        for (int o = 16; o; o >>= 1) s += __shfl_xor_sync(~0u, s, o);
        if (lane == 0) g_styles[gw] = s * 0.04419417382415922f + ab[j];
        return;
    }
    // ---- phase-composed 3x3 kernels (half2 writes) + wsq table ----
    int co = blockIdx.x - P1_STYLES, t = threadIdx.x;   // t = ci pair 0..255
    int ci0 = 2 * t;
    float wgt[2][3][3];
    float wsq[2] = {0.f, 0.f};
    #pragma unroll
    for (int h = 0; h < 2; h++) {
        const float* p = weight + ((size_t)co * C_ + ci0 + h) * 9;
        #pragma unroll
        for (int k = 0; k < 9; k++) {
            float v = p[k];
            wgt[h][k / 3][k % 3] = v;
            wsq[h] += v * v;
        }
    }
    *(float2*)(g_wsq + (size_t)co * C_ + ci0) = make_float2(wsq[0], wsq[1]);
    const float cc[4] = {1.f, 3.f, 3.f, 1.f};
    #pragma unroll
    for (int ry = 0; ry < 2; ry++)
    #pragma unroll
    for (int rx = 0; rx < 2; rx++) {
        int ph = ry * 2 + rx;
        #pragma unroll
        for (int dyi = 0; dyi < 3; dyi++)
        #pragma unroll
        for (int dxi = 0; dxi < 3; dxi++) {
            float v[2] = {0.f, 0.f};
            #pragma unroll
            for (int sy = 0; sy < 3; sy++) {
                int uy = 2 * dyi + 1 - ry - sy;
                if (uy < 0 || uy > 3) continue;
                #pragma unroll
                for (int sx = 0; sx < 3; sx++) {
                    int ux = 2 * dxi + 1 - rx - sx;
                    if (ux < 0 || ux > 3) continue;
                    float c = cc[uy] * cc[ux];
                    v[0] += wgt[0][2 - sy][2 - sx] * c;
                    v[1] += wgt[1][2 - sy][2 - sx] * c;
                }
            }
            int tap = dyi * 3 + dxi;
            __half2 h = __floats2half2_rn(v[0] * 0.0625f, v[1] * 0.0625f);
            *(__half2*)(g_pwh + (((size_t)(ph * 9 + tap) * C_) + co) * C_ + ci0) = h;
        }
    }
}

// prep2: blocks [0,1024): dcoef ; blocks [1024,2048): modulated-input repack.
#define P2_DCOEF 1024
__global__ void k_prep2(const float* __restrict__ x) {
    if (blockIdx.x < P2_DCOEF) {
        int gw = blockIdx.x * 8 + (threadIdx.x >> 5);  // (b, co), 8192 warps
        int lane = threadIdx.x & 31;
        int b = gw >> 9, co = gw & 511;
        const float4* wq = (const float4*)(g_wsq + (size_t)co * C_);
        const float4* sp = (const float4*)(g_styles + b * C_);
        float s = 0.f;
        #pragma unroll
        for (int i = 0; i < 4; i++) {
            float4 a = wq[lane + 32 * i], xv = sp[lane + 32 * i];
            s += a.x * xv.x * xv.x + a.y * xv.y * xv.y
               + a.z * xv.z * xv.z + a.w * xv.w * xv.w;
        }
        #pragma unroll
        for (int o = 16; o; o >>= 1) s += __shfl_xor_sync(~0u, s, o);
        if (lane == 0) g_dcoef[gw] = rsqrtf(s + 1e-8f);
        return;
    }
    // ---- modulated input -> kp-grouped half2 layout ----
    int bg = blockIdx.x - P2_DCOEF;            // b*64 + cg
    int b = bg >> 6, cg = bg & 63;
    float st[8];
    #pragma unroll
    for (int j = 0; j < 8; j++) st[j] = g_styles[b * C_ + cg * 8 + j];
    const float* src = x + ((size_t)(b * C_ + cg * 8)) * (HIN * HIN);
    uint4* dst = (uint4*)g_xs3 + (size_t)bg * (HIN * HIN);
    for (int i = threadIdx.x; i < HIN * HIN; i += 256) {
        uint4 o;
        __half2 h0 = __floats2half2_rn(src[i] * st[0], src[i + 1024] * st[1]);
        __half2 h1 = __floats2half2_rn(src[i + 2048] * st[2], src[i + 3072] * st[3]);
        __half2 h2 = __floats2half2_rn(src[i + 4096] * st[4], src[i + 5120] * st[5]);
        __half2 h3 = __floats2half2_rn(src[i + 6144] * st[6], src[i + 7168] * st[7]);
        o.x = *(uint32_t*)&h0; o.y = *(uint32_t*)&h1;
        o.z = *(uint32_t*)&h2; o.w = *(uint32_t*)&h3;
        dst[i] = o;
    }
}

// ======================= main MMA conv =====================================
// CTA 128co x 256px (8 q-rows), 256 threads (8 warps, 2M x 4N), warp 64x64.
// K loop: 16 chunks of 32 ci (4 cg groups); ldmatrix operand loads.
#define NCH   16
#define ACO2  20                      // A co stride (words): 16 data + 4 pad
#define A_WORDS (9 * 128 * ACO2)      // 23040 u32
#define A_TAP_BYTES (128 * ACO2 * 4)  // 10240
#define B_WORDS (4 * 340 * 4)         // 5440 u32 (cg x 10 x 34 x kp)
#define BUF_WORDS (A_WORDS + B_WORDS) // 28480
#define BUF_BYTES (BUF_WORDS * 4)     // 113920
#define NSTAGE 2
#define SMEM_DYN (NSTAGE * BUF_BYTES) // 227840

__global__ void __launch_bounds__(256, 1)
k_conv_mma(const float* __restrict__ bias,
           const float* __restrict__ noise,
           const float* __restrict__ nstr,
           float* __restrict__ out) {
    extern __shared__ uint32_t dsm[];
    const uint32_t sbase = smem_u32(dsm);

    const int tid  = threadIdx.x;
    const int lane = tid & 31;
    const int wid  = tid >> 5;
    const int wm   = (wid & 1) * 64;          // warp co offset
    const int wn   = (wid >> 1) * 64;         // warp pix offset
    const int g    = lane >> 2;
    const int tg   = lane & 3;

    const int co0 = blockIdx.x * 128;
    const int qy0 = blockIdx.y * 8;
    const int bz  = blockIdx.z;
    const int b   = bz >> 2, ph = bz & 3;
    const int ry  = ph >> 1, rx = ph & 1;

    const uint32_t* xs_b = g_xs3 + (size_t)(b * 64) * (HIN * HIN * 4);
    const __half*   pw_p = g_pwh + (size_t)ph * 9 * C_ * C_;

    // ldmatrix lane address bases (byte offsets within tile regions)
    const uint32_t a_lane = (uint32_t)((wm + (lane & 15)) * (ACO2 * 4) + (lane >> 4) * 16);
    const uint32_t b_lane = (uint32_t)((lane >> 3) * (340 * 16) + (lane & 7) * 16);

    float acc[4][8][4];
    #pragma unroll
    for (int mf = 0; mf < 4; mf++)
        #pragma unroll
        for (int nf = 0; nf < 8; nf++)
            #pragma unroll
            for (int r = 0; r < 4; r++) acc[mf][nf][r] = 0.f;

    // ---- chunk loader (cp.async into stage s); chunk = 32 ci = 4 cg ----
    auto load_chunk = [&](int it, int s) {
        const int ci0 = it * 32;
        const uint32_t ab = sbase + s * BUF_BYTES;
        const uint32_t bb = ab + A_WORDS * 4;
        // A: 9 taps x 128 co x 32 ci (4 cp16 per co-row; row stride 20 words)
        #pragma unroll
        for (int j = 0; j < 18; j++) {
            int idx = j * 256 + tid;          // 0..4607
            int row = idx >> 2;               // tap*128 + co
            int h   = idx & 3;
            int tap = row >> 7;
            int co  = row & 127;
            cp16(ab + (uint32_t)((row * ACO2 + h * 4) * 4),
                 pw_p + ((size_t)tap * C_ + co0 + co) * C_ + ci0 + h * 8);
        }
        // B: 4 cg x 10 rows x 34 cols, one cp16 per (cg,y,x) position
        #pragma unroll
        for (int j = 0; j < 6; j++) {
            int e = j * 256 + tid;
            if (j == 5 && e >= 1360) break;
            int cg  = e / 340;
            int rem = e - cg * 340;
            int row = rem / 34;
            int col = rem - row * 34;
            int gy = qy0 + row - 1;
            int gx = col - 1;
            bool ok = ((unsigned)gy < (unsigned)HIN) & ((unsigned)gx < (unsigned)HIN);
            cp16z(bb + (uint32_t)((cg * 340 + row * 34 + col) * 16),
                  xs_b + (((size_t)(it * 4 + cg)) * (HIN * HIN) + gy * HIN + gx) * 4, ok);
        }
    };

    load_chunk(0, 0); CP_COMMIT();

    int stage = 0;
    for (int it = 0; it < NCH; ++it) {
        __syncthreads();
        if (it + 1 < NCH) {
            load_chunk(it + 1, stage ^ 1);
            CP_COMMIT();
            CP_WAIT1();
        } else {
            CP_WAIT0();
        }
        __syncthreads();

        const uint32_t sA = sbase + stage * BUF_BYTES;
        const uint32_t sBb = sA + A_WORDS * 4;

        #pragma unroll
        for (int tap = 0; tap < 9; tap++) {
            const int dy = tap / 3, dx = tap - 3 * (tap / 3);
            const uint32_t at = sA + tap * A_TAP_BYTES + a_lane;
            uint32_t af[4][8];
            #pragma unroll
            for (int mf = 0; mf < 4; mf++) {
                ldsm4(af[mf],     at + mf * (16 * ACO2 * 4));        // kseg0
                ldsm4(af[mf] + 4, at + mf * (16 * ACO2 * 4) + 32);   // kseg1
            }
            const uint32_t bt = sBb + b_lane + (uint32_t)((dy * 34 + dx) * 16);
            #pragma unroll
            for (int nf = 0; nf < 8; nf++) {
                int n0 = wn + nf * 8;
                uint32_t bf[4];
                ldsm4(bf, bt + (uint32_t)((((n0 >> 5) * 34) + (n0 & 31)) * 16));
                #pragma unroll
                for (int mf = 0; mf < 4; mf++) {
                    mma16(acc[mf][nf], af[mf], bf);
                    mma16(acc[mf][nf], af[mf] + 4, bf + 2);
                }
            }
        }

        stage ^= 1;
    }

    // ---- epilogue: demod + noise + bias + lrelu*sqrt(2) ----
    const float ns = *nstr;
    int baseo[8];
    float nz0[8], nz1[8];
    #pragma unroll
    for (int nf = 0; nf < 8; nf++) {
        int n0 = wn + nf * 8 + 2 * tg;
        int oy = 2 * (qy0 + (n0 >> 5)) + ry;
        int ox = 2 * (n0 & 31) + rx;
        baseo[nf] = oy * RESO + ox;
        nz0[nf] = noise[baseo[nf]] * ns;
        nz1[nf] = noise[baseo[nf] + 2] * ns;
    }
    #pragma unroll
    for (int mf = 0; mf < 4; mf++) {
        int co_a = co0 + wm + mf * 16 + g;
        int co_b = co_a + 8;
        float dca = g_dcoef[b * C_ + co_a], bva = bias[co_a];
        float dcb = g_dcoef[b * C_ + co_b], bvb = bias[co_b];
        float* oa = out + ((size_t)(b * C_ + co_a) * RESO) * RESO;
        float* ob = out + ((size_t)(b * C_ + co_b) * RESO) * RESO;
        #pragma unroll
        for (int nf = 0; nf < 8; nf++) {
            int base = baseo[nf];
            float v0 = acc[mf][nf][0] * dca + nz0[nf] + bva;
            float v1 = acc[mf][nf][1] * dca + nz1[nf] + bva;
            float v2 = acc[mf][nf][2] * dcb + nz0[nf] + bvb;
            float v3 = acc[mf][nf][3] * dcb + nz1[nf] + bvb;
            v0 = (v0 >= 0.f ? v0 : 0.2f * v0) * 1.4142135623730951f;
            v1 = (v1 >= 0.f ? v1 : 0.2f * v1) * 1.4142135623730951f;
            v2 = (v2 >= 0.f ? v2 : 0.2f * v2) * 1.4142135623730951f;
            v3 = (v3 >= 0.f ? v3 : 0.2f * v3) * 1.4142135623730951f;
            oa[base]     = v0;
            oa[base + 2] = v1;
            ob[base]     = v2;
            ob[base + 2] = v3;
        }
    }
}

// ======================= launch ============================================
extern "C" void kernel_launch(void* const* d_in, const int* in_sizes, int n_in,
                              void* d_out, int out_size) {
    const float* x      = (const float*)d_in[0];
    const float* w      = (const float*)d_in[1];
    const float* aw     = (const float*)d_in[2];
    const float* ab     = (const float*)d_in[3];
    const float* weight = (const float*)d_in[4];
    const float* bias   = (const float*)d_in[5];
    const float* noise  = (const float*)d_in[6];
    const float* nstr   = (const float*)d_in[7];
    float* out = (float*)d_out;

    static bool attr_set = false;
    if (!attr_set) {
        cudaFuncSetAttribute(k_conv_mma,
                             cudaFuncAttributeMaxDynamicSharedMemorySize, SMEM_DYN);
        attr_set = true;
    }

    k_prep1<<<P1_STYLES + C_, 256>>>(w, aw, ab, weight);
    k_prep2<<<P2_DCOEF + B_ * 64, 256>>>(x);
    k_conv_mma<<<dim3(4, 4, B_ * 4), 256, SMEM_DYN>>>(bias, noise, nstr, out);
}